// round 16
// baseline (speedup 1.0000x reference)
#include <cuda_runtime.h>
#include <math.h>

#define Tn 4
#define Bn 4
#define Cn 64
#define Ln 4096
#define NLAYERS 10
#define TL 128         // l-tile per block -> grid 32x4 = 128 = single wave
#define LTHREADS 512
#define RCP_TAU (1.0f/1.2f)

// ---------------- scratch (no allocations allowed) ----------------
__device__ float g_xA[Tn*Bn*Cn*Ln];     // 16 MB
__device__ float g_xB[Tn*Bn*Cn*Ln];     // 16 MB
__device__ float g_skip[Tn*Bn*Cn*Ln];   // 16 MB
__device__ float g_proj[NLAYERS*Bn*Cn];

// ---------------- packed f32x2 helpers ----------------
__device__ __forceinline__ unsigned long long pk2(float w){
    unsigned long long r;
    asm("mov.b64 %0, {%1, %1};" : "=l"(r) : "f"(w));
    return r;
}
__device__ __forceinline__ void f2fma(unsigned long long &d, unsigned long long a, unsigned long long b){
    asm("fma.rn.f32x2 %0, %1, %2, %0;" : "+l"(d) : "l"(a), "l"(b));
}
__device__ __forceinline__ float lo32(unsigned long long v){ return __uint_as_float((unsigned)v); }
__device__ __forceinline__ float hi32(unsigned long long v){ return __uint_as_float((unsigned)(v>>32)); }

__device__ __forceinline__ void lif_step(float &v, float x, float &spike){
    v = fmaf(x - v, RCP_TAU, v);
    spike = (v >= 0.5f) ? 1.f : 0.f;
    v *= (1.f - spike);
}

// ---------------- JAX threefry2x32 (key = (0,42)) ----------------
__device__ __forceinline__ unsigned rotl32(unsigned x, int r){ return (x<<r)|(x>>(32-r)); }

__device__ __forceinline__ void threefry_0_42(unsigned x0, unsigned x1, unsigned &o0, unsigned &o1){
    const unsigned ks0 = 0u, ks1 = 42u, ks2 = 0u ^ 42u ^ 0x1BD11BDAu;
    x0 += ks0; x1 += ks1;
#define TF_RND(r) { x0 += x1; x1 = rotl32(x1,(r)); x1 ^= x0; }
    TF_RND(13) TF_RND(15) TF_RND(26) TF_RND(6)
    x0 += ks1; x1 += ks2 + 1u;
    TF_RND(17) TF_RND(29) TF_RND(16) TF_RND(24)
    x0 += ks2; x1 += ks0 + 2u;
    TF_RND(13) TF_RND(15) TF_RND(26) TF_RND(6)
    x0 += ks0; x1 += ks1 + 3u;
    TF_RND(17) TF_RND(29) TF_RND(16) TF_RND(24)
    x0 += ks1; x1 += ks2 + 4u;
    TF_RND(13) TF_RND(15) TF_RND(26) TF_RND(6)
    x0 += ks2; x1 += ks0 + 5u;
#undef TF_RND
    o0 = x0; o1 = x1;
}
__device__ __forceinline__ float bits2unit(unsigned b){
    return __uint_as_float((b >> 9) | 0x3f800000u) - 1.0f;
}

// ---------------- encoder ----------------
__global__ void __launch_bounds__(256) enc_kernel(const float* __restrict__ audio,
                                                  const float* __restrict__ w_in,
                                                  const float* __restrict__ b_in){
    int g = blockIdx.x * 256 + threadIdx.x;
    int b = g >> 12, l = g & (Ln - 1);
    float a = audio[g];

    unsigned n0 = (unsigned)(b * Ln + l);
    unsigned o0, o1, o2, o3;
    threefry_0_42(n0,           n0 + 32768u, o0, o2);
    threefry_0_42(n0 + 16384u,  n0 + 49152u, o1, o3);

    float sp[4];
    sp[0] = (bits2unit(o0) < a) ? 1.f : 0.f;
    sp[1] = (bits2unit(o1) < a) ? 1.f : 0.f;
    sp[2] = (bits2unit(o2) < a) ? 1.f : 0.f;
    sp[3] = (bits2unit(o3) < a) ? 1.f : 0.f;

    for (int c = 0; c < Cn; c++){
        float w = w_in[c], bi = b_in[c];
        float v = 0.f;
#pragma unroll
        for (int t = 0; t < Tn; t++){
            float x = w * sp[t] + bi;
            float s; lif_step(v, x, s);
            int idx = ((t*Bn + b)*Cn + c)*Ln + l;
            g_xA[idx] = s;
        }
    }
}

// ---------------- ALL layers' diffusion-step embedding + projection ----------------
__global__ void __launch_bounds__(256) proj_all_kernel(const int* __restrict__ dstep,
                                                       const float* __restrict__ w1a,
                                                       const float* __restrict__ b1a,
                                                       const float* __restrict__ w2a,
                                                       const float* __restrict__ b2a,
                                                       const float* __restrict__ dpwa,
                                                       const float* __restrict__ dpba){
    int i = blockIdx.x;
    const float* w1 = w1a + i*Cn;
    const float* b1 = b1a + i*Cn;
    const float* w2 = w2a + i*Cn*Cn;
    const float* b2 = b2a + i*Cn;
    const float* dpw = dpwa + i*Cn*Cn;
    const float* dpb = dpba + i*Cn;

    __shared__ float h[Bn][Cn];
    __shared__ float e[Bn][Cn];
    int tid = threadIdx.x;
    int b = tid >> 6, c = tid & 63;

    float d = (float)dstep[b];
    float z = d * w1[c] + b1[c];
    float sg = 1.f / (1.f + expf(-z));
    h[b][c] = z * sg;
    __syncthreads();

    float acc = b2[c];
    for (int j = 0; j < Cn; j++) acc += h[b][j] * w2[c*Cn + j];
    e[b][c] = acc;
    __syncthreads();

    float p = dpb[c];
    for (int j = 0; j < Cn; j++) p += e[b][j] * dpw[c*Cn + j];
    g_proj[i*Bn*Cn + b*Cn + c] = p;
}

// ---------------- fused layer: TL=128, 1 timestep/pass, split-staged pipeline ----
// 512 threads: lg = tid&31 -> jA = lg*4 (4 l); jg = tid>>5 (couts jg+16m, m=0..7)
__global__ void __launch_bounds__(LTHREADS, 1) layer_kernel(int flip, int layer,
                                                       const float* __restrict__ wconv,
                                                       const float* __restrict__ bconv,
                                                       const float* __restrict__ wskip,
                                                       const float* __restrict__ bskip,
                                                       const float* __restrict__ wres,
                                                       const float* __restrict__ bres,
                                                       int dil){
    const float* x_in  = flip ? g_xB : g_xA;
    float*       x_out = flip ? g_xA : g_xB;

    extern __shared__ float sm[];
    float* wc8  = sm;            // [ci][16 jg][3 tap][8 m]               24576
    float* wskr = wc8  + 24576;  // [ci][16 jg][s:4, r:4]                  8192
    float* cb   = wskr + 8192;   // raw conv bias -> rearranged folded bias 128
    float* pr   = cb   + 128;    // 64
    float* sbv  = pr   + 64;     // 64
    float* rbv  = sbv  + 64;     // 64
    float* ck   = rbv  + 64;     // [3][128] proj-fold constants           384
    float* tile = ck   + 384;    // 3 shifts x [64 ci][128 l] = 24576
                                 // gated overlay -> s0 region after conv
                                 // total = 58048 floats = 232192 B

    const int tid  = threadIdx.x;
    const int b    = blockIdx.y;
    const int l0   = blockIdx.x * TL;
    const int lg   = tid & 31;
    const int jg   = tid >> 5;     // 0..15
    const int jA   = lg * 4;

    // ---- coalesced weight load + scatter repack ----
    for (int i = tid; i < 24576; i += LTHREADS){
        int co = i / 192, r = i % 192, ci = r / 3, k = r % 3;
        int jgc = co & 15, mc = co >> 4;
        wc8[((ci*16 + jgc)*3 + k)*8 + mc] = wconv[i];
    }
    for (int i = tid; i < 4096; i += LTHREADS){
        int co = i >> 6, ci = i & 63;
        int jgc = co & 15, mc = co >> 4;     // mc 0..3
        wskr[(ci*16 + jgc)*8 + mc    ] = wskip[i];
        wskr[(ci*16 + jgc)*8 + 4 + mc] = wres[i];
    }
    if (tid < 128) cb[tid] = bconv[tid];
    if (tid < 64){
        pr[tid]  = g_proj[layer*Bn*Cn + b*Cn + tid];
        sbv[tid] = bskip[tid];
        rbv[tid] = bres[tid];
    }
    __syncthreads();

    // ---- proj-fold constants ----
    if (tid < 384){
        int k = tid >> 7;
        int cout = tid & 127;
        int jgc = cout & 15, mc = cout >> 4;
        float acc = 0.f;
        for (int ci = 0; ci < Cn; ci++)
            acc += wc8[((ci*16 + jgc)*3 + k)*8 + mc] * pr[ci];
        ck[(k << 7) + cout] = acc;
    }
    __syncthreads();

    // ---- folded bias rearranged into cb[(jg<<3)+m] ----
    float fbv = 0.f;
    if (tid < 128){
        int c = tid;
        fbv = cb[c] + ck[c] + ck[128+c] + ck[256+c];
    }
    __syncthreads();
    if (tid < 128){
        int c = tid;
        cb[((c & 15) << 3) + (c >> 4)] = fbv;
    }
    __syncthreads();

    const float SG1 = 1.f / (1.f + expf(-1.f));
    const float TH1 = tanhf(1.f);
    const bool edge = (l0 < dil) || (l0 + TL + dil > Ln);
    const bool async_path = (dil >= 4);

    // LIF state: gate/filt, lo/hi co halves, [p*4 + l]
    float vG0[8], vG1[8], vF0[8], vF1[8];
#pragma unroll
    for (int k = 0; k < 8; k++){ vG0[k]=0.f; vG1[k]=0.f; vF0[k]=0.f; vF1[k]=0.f; }

    // ---- prologue: full staging for t=0 ----
    {
        const float* xk = x_in + ((size_t)(0*Bn + b)) * Cn * Ln;
        if (async_path){
#pragma unroll
            for (int w = 0; w < 12; w++){
                int q  = tid + w*LTHREADS;
                int s  = q >> 11;
                int r  = q & 2047;
                int ci = r >> 5;
                int jc = (r & 31) << 2;
                int gl = l0 + (s - 1)*dil + jc;
                unsigned ss = ((unsigned)gl <= 4092u) ? 16u : 0u;
                const float* src = ss ? (xk + ci*Ln + gl) : xk;
                unsigned daddr = (unsigned)__cvta_generic_to_shared(
                                     tile + (s << 13) + (ci << 7) + jc);
                asm volatile("cp.async.ca.shared.global [%0], [%1], 16, %2;"
                             :: "r"(daddr), "l"(src), "r"(ss) : "memory");
            }
            asm volatile("cp.async.commit_group;" ::: "memory");
            asm volatile("cp.async.wait_group 0;" ::: "memory");
        } else {
#pragma unroll 4
            for (int i = tid; i < 3*Cn*TL; i += LTHREADS){
                int s  = i >> 13;
                int r  = i & 8191;
                int ci = r >> 7; int j = r & 127;
                int gl = l0 + j + (s - 1) * dil;
                float val = 0.f;
                if ((unsigned)gl < (unsigned)Ln) val = xk[ci*Ln + gl];
                tile[i] = val;
            }
        }
    }
    __syncthreads();   // S1 (t=0)

    for (int t = 0; t < Tn; t++){
        const float* xk_next = x_in + ((size_t)((t+1)*Bn + b)) * Cn * Ln;

        // ---- conv: 16 couts x 4 l, this timestep ----
        unsigned long long acc[4][4];   // [m-pair p][l]
        {
            const ulonglong2* fb = (const ulonglong2*)(cb + (jg << 3));
            ulonglong2 fbA = fb[0], fbB = fb[1];
#pragma unroll
            for (int l = 0; l < 4; l++){
                acc[0][l] = fbA.x; acc[1][l] = fbA.y;
                acc[2][l] = fbB.x; acc[3][l] = fbB.y;
            }
        }
#pragma unroll 2
        for (int ci = 0; ci < Cn; ci++){
            const float* trow = tile + (ci << 7);
            ulonglong2 xa = *(const ulonglong2*)(trow + jA);
            ulonglong2 xz = *(const ulonglong2*)(trow + 8192 + jA);
            ulonglong2 xp = *(const ulonglong2*)(trow + 16384 + jA);
            const float* wrow = wc8 + (ci*16 + jg)*24;
#pragma unroll
            for (int tap = 0; tap < 3; tap++){
                ulonglong2 wA = *(const ulonglong2*)(wrow + tap*8);
                ulonglong2 wB = *(const ulonglong2*)(wrow + tap*8 + 4);
                ulonglong2 xs_ = (tap == 0) ? xa : (tap == 1) ? xz : xp;
                unsigned long long xd0 = pk2(lo32(xs_.x));
                unsigned long long xd1 = pk2(hi32(xs_.x));
                unsigned long long xd2 = pk2(lo32(xs_.y));
                unsigned long long xd3 = pk2(hi32(xs_.y));
                f2fma(acc[0][0], wA.x, xd0); f2fma(acc[0][1], wA.x, xd1);
                f2fma(acc[0][2], wA.x, xd2); f2fma(acc[0][3], wA.x, xd3);
                f2fma(acc[1][0], wA.y, xd0); f2fma(acc[1][1], wA.y, xd1);
                f2fma(acc[1][2], wA.y, xd2); f2fma(acc[1][3], wA.y, xd3);
                f2fma(acc[2][0], wB.x, xd0); f2fma(acc[2][1], wB.x, xd1);
                f2fma(acc[2][2], wB.x, xd2); f2fma(acc[2][3], wB.x, xd3);
                f2fma(acc[3][0], wB.y, xd0); f2fma(acc[3][1], wB.y, xd1);
                f2fma(acc[3][2], wB.y, xd2); f2fma(acc[3][3], wB.y, xd3);
            }
        }

        // ---- LIF + gating (ALL threads, own accs) ----
        float glo[2][4], ghi[2][4];
#pragma unroll
        for (int p = 0; p < 2; p++){
#pragma unroll
            for (int l = 0; l < 4; l++){
                float ag_lo = lo32(acc[p][l]),   ag_hi = hi32(acc[p][l]);
                float af_lo = lo32(acc[p+2][l]), af_hi = hi32(acc[p+2][l]);

                if (edge){
                    int gl = l0 + jA + l;
                    float f0 = (gl < dil) ? 1.f : 0.f;
                    float f2 = (gl >= Ln - dil) ? 1.f : 0.f;
                    int clo = jg + 32*p;
                    ag_lo -= f0*ck[clo]      + f2*ck[256+clo];
                    ag_hi -= f0*ck[clo+16]   + f2*ck[256+clo+16];
                    af_lo -= f0*ck[clo+64]   + f2*ck[256+clo+64];
                    af_hi -= f0*ck[clo+80]   + f2*ck[256+clo+80];
                }

                int idx = p*4 + l;
                float sg, sf;
                lif_step(vG0[idx], ag_lo, sg); lif_step(vF0[idx], af_lo, sf);
                glo[p][l] = ((sg > 0.f) ? SG1 : 0.5f) * ((sf > 0.f) ? TH1 : 0.f);
                lif_step(vG1[idx], ag_hi, sg); lif_step(vF1[idx], af_hi, sf);
                ghi[p][l] = ((sg > 0.f) ? SG1 : 0.5f) * ((sf > 0.f) ? TH1 : 0.f);
            }
        }
        __syncthreads();   // S2: conv tile reads done -> s0 overlay safe, s2 dead

#pragma unroll
        for (int p = 0; p < 2; p++){
            int chlo = jg + 32*p;
            int chhi = chlo + 16;
            *(float4*)(tile + (chlo << 7) + jA) = make_float4(glo[p][0], glo[p][1], glo[p][2], glo[p][3]);
            *(float4*)(tile + (chhi << 7) + jA) = make_float4(ghi[p][0], ghi[p][1], ghi[p][2], ghi[p][3]);
        }
        __syncthreads();   // S3: gated overlay visible

        // ---- EARLY staging: next pass's s2 (plus-tap) region, overlapped with 1x1 ----
        if (t < Tn-1 && async_path){
#pragma unroll
            for (int w = 0; w < 4; w++){
                int q  = tid + w*LTHREADS;    // 0..2047 chunks of s2
                int ci = q >> 5;
                int jc = (q & 31) << 2;
                int gl = l0 + dil + jc;
                unsigned ss = ((unsigned)gl <= 4092u) ? 16u : 0u;
                const float* src = ss ? (xk_next + ci*Ln + gl) : xk_next;
                unsigned daddr = (unsigned)__cvta_generic_to_shared(
                                     tile + (2 << 13) + (ci << 7) + jc);
                asm volatile("cp.async.ca.shared.global [%0], [%1], 16, %2;"
                             :: "r"(daddr), "l"(src), "r"(ss) : "memory");
            }
            asm volatile("cp.async.commit_group;" ::: "memory");
        }

        // ---- skip / res 1x1: 4 couts (jg+16m1) x 4 l ----
        unsigned long long sk[2][4], rs[2][4];
#pragma unroll
        for (int p = 0; p < 2; p++)
#pragma unroll
        for (int l = 0; l < 4; l++){ sk[p][l] = 0ull; rs[p][l] = 0ull; }

#pragma unroll 4
        for (int ci = 0; ci < Cn; ci++){
            ulonglong2 g = *(const ulonglong2*)(tile + (ci << 7) + jA);
            unsigned long long gd0 = pk2(lo32(g.x));
            unsigned long long gd1 = pk2(hi32(g.x));
            unsigned long long gd2 = pk2(lo32(g.y));
            unsigned long long gd3 = pk2(hi32(g.y));
            const float* wb = wskr + (ci*16 + jg)*8;
            ulonglong2 wsv = *(const ulonglong2*)(wb);
            ulonglong2 wrv = *(const ulonglong2*)(wb + 4);
            f2fma(sk[0][0], wsv.x, gd0); f2fma(sk[0][1], wsv.x, gd1);
            f2fma(sk[0][2], wsv.x, gd2); f2fma(sk[0][3], wsv.x, gd3);
            f2fma(sk[1][0], wsv.y, gd0); f2fma(sk[1][1], wsv.y, gd1);
            f2fma(sk[1][2], wsv.y, gd2); f2fma(sk[1][3], wsv.y, gd3);
            f2fma(rs[0][0], wrv.x, gd0); f2fma(rs[0][1], wrv.x, gd1);
            f2fma(rs[0][2], wrv.x, gd2); f2fma(rs[0][3], wrv.x, gd3);
            f2fma(rs[1][0], wrv.y, gd0); f2fma(rs[1][1], wrv.y, gd1);
            f2fma(rs[1][2], wrv.y, gd2); f2fma(rs[1][3], wrv.y, gd3);
        }

        // ---- global update: 4 ch x 4 l ----
        {
#pragma unroll
            for (int m = 0; m < 4; m++){
                int ch = jg + 16*m;
                int p = m >> 1;
                bool hi = (m & 1);
                float s0 = hi ? hi32(sk[p][0]) : lo32(sk[p][0]);
                float s1 = hi ? hi32(sk[p][1]) : lo32(sk[p][1]);
                float s2 = hi ? hi32(sk[p][2]) : lo32(sk[p][2]);
                float s3 = hi ? hi32(sk[p][3]) : lo32(sk[p][3]);
                float r0 = hi ? hi32(rs[p][0]) : lo32(rs[p][0]);
                float r1 = hi ? hi32(rs[p][1]) : lo32(rs[p][1]);
                float r2 = hi ? hi32(rs[p][2]) : lo32(rs[p][2]);
                float r3 = hi ? hi32(rs[p][3]) : lo32(rs[p][3]);
                float sbp = sbv[ch], rbp = rbv[ch];
                size_t gbase = ((size_t)(t*Bn + b)*Cn + ch)*Ln + l0 + jA;

                float4 sv = make_float4(s0+sbp, s1+sbp, s2+sbp, s3+sbp);
                float4* skA = (float4*)(g_skip + gbase);
                if (layer != 0){
                    float4 o0 = *skA;
                    sv.x += o0.x; sv.y += o0.y; sv.z += o0.z; sv.w += o0.w;
                }
                *skA = sv;

                if (layer != NLAYERS-1){
                    float4 a0 = *(const float4*)(tile + 8192 + (ch << 7) + jA);
                    a0.x += r0+rbp; a0.y += r1+rbp; a0.z += r2+rbp; a0.w += r3+rbp;
                    *(float4*)(x_out + gbase) = a0;
                }
            }
        }

        // ---- LATE staging (only if another pass follows) ----
        if (t < Tn-1){
            __syncthreads();   // S4: all tile reads done -> staging safe
            if (async_path){
#pragma unroll
                for (int w = 0; w < 8; w++){
                    int q  = tid + w*LTHREADS;   // 0..4095 chunks over s0,s1
                    int s  = q >> 11;            // 0 or 1
                    int r  = q & 2047;
                    int ci = r >> 5;
                    int jc = (r & 31) << 2;
                    int gl = l0 + (s - 1)*dil + jc;
                    unsigned ss = ((unsigned)gl <= 4092u) ? 16u : 0u;
                    const float* src = ss ? (xk_next + ci*Ln + gl) : xk_next;
                    unsigned daddr = (unsigned)__cvta_generic_to_shared(
                                         tile + (s << 13) + (ci << 7) + jc);
                    asm volatile("cp.async.ca.shared.global [%0], [%1], 16, %2;"
                                 :: "r"(daddr), "l"(src), "r"(ss) : "memory");
                }
                asm volatile("cp.async.commit_group;" ::: "memory");
                asm volatile("cp.async.wait_group 0;" ::: "memory");
            } else {
#pragma unroll 4
                for (int i = tid; i < 3*Cn*TL; i += LTHREADS){
                    int s  = i >> 13;
                    int r  = i & 8191;
                    int ci = r >> 7; int j = r & 127;
                    int gl = l0 + j + (s - 1) * dil;
                    float val = 0.f;
                    if ((unsigned)gl < (unsigned)Ln) val = xk_next[ci*Ln + gl];
                    tile[i] = val;
                }
            }
            __syncthreads();   // S1 of next pass
        }
    }
}

// ---------------- final: relu(skip) -> 1x1 conv -> LIF -> sum over T (4 l/thread) ----
__global__ void __launch_bounds__(256) out_kernel(const float* __restrict__ wout,
                                                  const float* __restrict__ bout,
                                                  float* __restrict__ out){
    int g = blockIdx.x * 256 + threadIdx.x;    // 0..4095
    int b = g >> 10;
    int l = (g & 1023) << 2;
    float bo = bout[0];
    float v0=0.f, v1=0.f, v2=0.f, v3=0.f;
    float s0=0.f, s1=0.f, s2=0.f, s3=0.f;
#pragma unroll
    for (int t = 0; t < Tn; t++){
        float4 acc = make_float4(bo, bo, bo, bo);
        const float* sk = g_skip + ((size_t)(t*Bn + b))*Cn*Ln + l;
        for (int c = 0; c < Cn; c++){
            float4 s4 = *(const float4*)(sk + ((size_t)c)*Ln);
            float w = wout[c];
            acc.x += w * fmaxf(s4.x, 0.f);
            acc.y += w * fmaxf(s4.y, 0.f);
            acc.z += w * fmaxf(s4.z, 0.f);
            acc.w += w * fmaxf(s4.w, 0.f);
        }
        float sp;
        lif_step(v0, acc.x, sp); s0 += sp;
        lif_step(v1, acc.y, sp); s1 += sp;
        lif_step(v2, acc.z, sp); s2 += sp;
        lif_step(v3, acc.w, sp); s3 += sp;
    }
    *(float4*)(out + ((size_t)g << 2)) = make_float4(s0, s1, s2, s3);
}

// ---------------- launch ----------------
extern "C" void kernel_launch(void* const* d_in, const int* in_sizes, int n_in,
                              void* d_out, int out_size){
    const float* audio   = (const float*)d_in[0];
    const int*   dstep   = (const int*)  d_in[1];
    const float* W_in    = (const float*)d_in[2];
    const float* b_in    = (const float*)d_in[3];
    const float* demb_w1 = (const float*)d_in[4];
    const float* demb_b1 = (const float*)d_in[5];
    const float* demb_w2 = (const float*)d_in[6];
    const float* demb_b2 = (const float*)d_in[7];
    const float* dproj_w = (const float*)d_in[8];
    const float* dproj_b = (const float*)d_in[9];
    const float* conv_w  = (const float*)d_in[10];
    const float* conv_b  = (const float*)d_in[11];
    const float* skip_w  = (const float*)d_in[12];
    const float* skip_b  = (const float*)d_in[13];
    const float* res_w   = (const float*)d_in[14];
    const float* res_b   = (const float*)d_in[15];
    const float* W_out   = (const float*)d_in[16];
    const float* b_out   = (const float*)d_in[17];

    const int SMEM_BYTES = 58048 * 4;   // 232192  (audited: 58048 floats)
    cudaFuncSetAttribute((const void*)layer_kernel,
                         cudaFuncAttributeMaxDynamicSharedMemorySize, SMEM_BYTES);

    enc_kernel<<<(Bn*Ln)/256, 256>>>(audio, W_in, b_in);

    proj_all_kernel<<<NLAYERS, 256>>>(dstep, demb_w1, demb_b1, demb_w2, demb_b2,
                                      dproj_w, dproj_b);

    int flip = 0;
    for (int i = 0; i < NLAYERS; i++){
        layer_kernel<<<dim3(Ln/TL, Bn), LTHREADS, SMEM_BYTES>>>(flip, i,
                                conv_w + i*2*Cn*Cn*3, conv_b + i*2*Cn,
                                skip_w + i*Cn*Cn,     skip_b + i*Cn,
                                res_w  + i*Cn*Cn,     res_b  + i*Cn,
                                1 << i);
        flip ^= 1;
    }

    out_kernel<<<(Bn*Ln/4)/256, 256>>>(W_out, b_out, (float*)d_out);
}

// round 17
// speedup vs baseline: 1.0978x; 1.0978x over previous
#include <cuda_runtime.h>
#include <math.h>

#define Tn 4
#define Bn 4
#define Cn 64
#define Ln 4096
#define NLAYERS 10
#define TL 128         // l-tile per block -> grid 32x4 = 128 = single wave
#define LTHREADS 512
#define RCP_TAU (1.0f/1.2f)

// ---------------- scratch (no allocations allowed) ----------------
__device__ float g_xA[Tn*Bn*Cn*Ln];     // 16 MB  (reused as out-stage scratch)
__device__ float g_xB[Tn*Bn*Cn*Ln];     // 16 MB
__device__ float g_skip[Tn*Bn*Cn*Ln];   // 16 MB
__device__ float g_proj[NLAYERS*Bn*Cn];

// ---------------- packed f32x2 helpers ----------------
__device__ __forceinline__ unsigned long long pk2(float w){
    unsigned long long r;
    asm("mov.b64 %0, {%1, %1};" : "=l"(r) : "f"(w));
    return r;
}
__device__ __forceinline__ void f2fma(unsigned long long &d, unsigned long long a, unsigned long long b){
    asm("fma.rn.f32x2 %0, %1, %2, %0;" : "+l"(d) : "l"(a), "l"(b));
}
__device__ __forceinline__ float lo32(unsigned long long v){ return __uint_as_float((unsigned)v); }
__device__ __forceinline__ float hi32(unsigned long long v){ return __uint_as_float((unsigned)(v>>32)); }

__device__ __forceinline__ void lif_step(float &v, float x, float &spike){
    v = fmaf(x - v, RCP_TAU, v);
    spike = (v >= 0.5f) ? 1.f : 0.f;
    v *= (1.f - spike);
}

// ---------------- JAX threefry2x32 (key = (0,42)) ----------------
__device__ __forceinline__ unsigned rotl32(unsigned x, int r){ return (x<<r)|(x>>(32-r)); }

__device__ __forceinline__ void threefry_0_42(unsigned x0, unsigned x1, unsigned &o0, unsigned &o1){
    const unsigned ks0 = 0u, ks1 = 42u, ks2 = 0u ^ 42u ^ 0x1BD11BDAu;
    x0 += ks0; x1 += ks1;
#define TF_RND(r) { x0 += x1; x1 = rotl32(x1,(r)); x1 ^= x0; }
    TF_RND(13) TF_RND(15) TF_RND(26) TF_RND(6)
    x0 += ks1; x1 += ks2 + 1u;
    TF_RND(17) TF_RND(29) TF_RND(16) TF_RND(24)
    x0 += ks2; x1 += ks0 + 2u;
    TF_RND(13) TF_RND(15) TF_RND(26) TF_RND(6)
    x0 += ks0; x1 += ks1 + 3u;
    TF_RND(17) TF_RND(29) TF_RND(16) TF_RND(24)
    x0 += ks1; x1 += ks2 + 4u;
    TF_RND(13) TF_RND(15) TF_RND(26) TF_RND(6)
    x0 += ks2; x1 += ks0 + 5u;
#undef TF_RND
    o0 = x0; o1 = x1;
}
__device__ __forceinline__ float bits2unit(unsigned b){
    return __uint_as_float((b >> 9) | 0x3f800000u) - 1.0f;
}

// ---------------- encoder ----------------
__global__ void __launch_bounds__(256) enc_kernel(const float* __restrict__ audio,
                                                  const float* __restrict__ w_in,
                                                  const float* __restrict__ b_in){
    int g = blockIdx.x * 256 + threadIdx.x;
    int b = g >> 12, l = g & (Ln - 1);
    float a = audio[g];

    unsigned n0 = (unsigned)(b * Ln + l);
    unsigned o0, o1, o2, o3;
    threefry_0_42(n0,           n0 + 32768u, o0, o2);
    threefry_0_42(n0 + 16384u,  n0 + 49152u, o1, o3);

    float sp[4];
    sp[0] = (bits2unit(o0) < a) ? 1.f : 0.f;
    sp[1] = (bits2unit(o1) < a) ? 1.f : 0.f;
    sp[2] = (bits2unit(o2) < a) ? 1.f : 0.f;
    sp[3] = (bits2unit(o3) < a) ? 1.f : 0.f;

    for (int c = 0; c < Cn; c++){
        float w = w_in[c], bi = b_in[c];
        float v = 0.f;
#pragma unroll
        for (int t = 0; t < Tn; t++){
            float x = w * sp[t] + bi;
            float s; lif_step(v, x, s);
            int idx = ((t*Bn + b)*Cn + c)*Ln + l;
            g_xA[idx] = s;
        }
    }
}

// ---------------- ALL layers' diffusion-step embedding + projection ----------------
__global__ void __launch_bounds__(256) proj_all_kernel(const int* __restrict__ dstep,
                                                       const float* __restrict__ w1a,
                                                       const float* __restrict__ b1a,
                                                       const float* __restrict__ w2a,
                                                       const float* __restrict__ b2a,
                                                       const float* __restrict__ dpwa,
                                                       const float* __restrict__ dpba){
    int i = blockIdx.x;
    const float* w1 = w1a + i*Cn;
    const float* b1 = b1a + i*Cn;
    const float* w2 = w2a + i*Cn*Cn;
    const float* b2 = b2a + i*Cn;
    const float* dpw = dpwa + i*Cn*Cn;
    const float* dpb = dpba + i*Cn;

    __shared__ float h[Bn][Cn];
    __shared__ float e[Bn][Cn];
    int tid = threadIdx.x;
    int b = tid >> 6, c = tid & 63;

    float d = (float)dstep[b];
    float z = d * w1[c] + b1[c];
    float sg = 1.f / (1.f + expf(-z));
    h[b][c] = z * sg;
    __syncthreads();

    float acc = b2[c];
    for (int j = 0; j < Cn; j++) acc += h[b][j] * w2[c*Cn + j];
    e[b][c] = acc;
    __syncthreads();

    float p = dpb[c];
    for (int j = 0; j < Cn; j++) p += e[b][j] * dpw[c*Cn + j];
    g_proj[i*Bn*Cn + b*Cn + c] = p;
}

// ---------------- fused layer: TL=128, 1 timestep/pass, split-staged pipeline ----
// (byte-identical to the R14 version that measured 1075.4 us total)
__global__ void __launch_bounds__(LTHREADS, 1) layer_kernel(int flip, int layer,
                                                       const float* __restrict__ wconv,
                                                       const float* __restrict__ bconv,
                                                       const float* __restrict__ wskip,
                                                       const float* __restrict__ bskip,
                                                       const float* __restrict__ wres,
                                                       const float* __restrict__ bres,
                                                       int dil){
    const float* x_in  = flip ? g_xB : g_xA;
    float*       x_out = flip ? g_xA : g_xB;

    extern __shared__ float sm[];
    float* wc8  = sm;            // [ci][16 jg][3 tap][8 m]               24576
    float* wskr = wc8  + 24576;  // [ci][16 jg][s:4, r:4]                  8192
    float* cb   = wskr + 8192;   // raw conv bias -> rearranged folded bias 128
    float* pr   = cb   + 128;    // 64
    float* sbv  = pr   + 64;     // 64
    float* rbv  = sbv  + 64;     // 64
    float* ck   = rbv  + 64;     // [3][128] proj-fold constants           384
    float* tile = ck   + 384;    // 3 shifts x [64 ci][128 l] = 24576
                                 // total = 58048 floats = 232192 B

    const int tid  = threadIdx.x;
    const int b    = blockIdx.y;
    const int l0   = blockIdx.x * TL;
    const int lg   = tid & 31;
    const int jg   = tid >> 5;     // 0..15
    const int jA   = lg * 4;

    // ---- coalesced weight load + scatter repack ----
    for (int i = tid; i < 24576; i += LTHREADS){
        int co = i / 192, r = i % 192, ci = r / 3, k = r % 3;
        int jgc = co & 15, mc = co >> 4;
        wc8[((ci*16 + jgc)*3 + k)*8 + mc] = wconv[i];
    }
    for (int i = tid; i < 4096; i += LTHREADS){
        int co = i >> 6, ci = i & 63;
        int jgc = co & 15, mc = co >> 4;     // mc 0..3
        wskr[(ci*16 + jgc)*8 + mc    ] = wskip[i];
        wskr[(ci*16 + jgc)*8 + 4 + mc] = wres[i];
    }
    if (tid < 128) cb[tid] = bconv[tid];
    if (tid < 64){
        pr[tid]  = g_proj[layer*Bn*Cn + b*Cn + tid];
        sbv[tid] = bskip[tid];
        rbv[tid] = bres[tid];
    }
    __syncthreads();

    // ---- proj-fold constants ----
    if (tid < 384){
        int k = tid >> 7;
        int cout = tid & 127;
        int jgc = cout & 15, mc = cout >> 4;
        float acc = 0.f;
        for (int ci = 0; ci < Cn; ci++)
            acc += wc8[((ci*16 + jgc)*3 + k)*8 + mc] * pr[ci];
        ck[(k << 7) + cout] = acc;
    }
    __syncthreads();

    // ---- folded bias rearranged into cb[(jg<<3)+m] ----
    float fbv = 0.f;
    if (tid < 128){
        int c = tid;
        fbv = cb[c] + ck[c] + ck[128+c] + ck[256+c];
    }
    __syncthreads();
    if (tid < 128){
        int c = tid;
        cb[((c & 15) << 3) + (c >> 4)] = fbv;
    }
    __syncthreads();

    const float SG1 = 1.f / (1.f + expf(-1.f));
    const float TH1 = tanhf(1.f);
    const bool edge = (l0 < dil) || (l0 + TL + dil > Ln);
    const bool async_path = (dil >= 4);

    // LIF state: gate/filt, lo/hi co halves, [p*4 + l]
    float vG0[8], vG1[8], vF0[8], vF1[8];
#pragma unroll
    for (int k = 0; k < 8; k++){ vG0[k]=0.f; vG1[k]=0.f; vF0[k]=0.f; vF1[k]=0.f; }

    // ---- prologue: full staging for t=0 ----
    {
        const float* xk = x_in + ((size_t)(0*Bn + b)) * Cn * Ln;
        if (async_path){
#pragma unroll
            for (int w = 0; w < 12; w++){
                int q  = tid + w*LTHREADS;
                int s  = q >> 11;
                int r  = q & 2047;
                int ci = r >> 5;
                int jc = (r & 31) << 2;
                int gl = l0 + (s - 1)*dil + jc;
                unsigned ss = ((unsigned)gl <= 4092u) ? 16u : 0u;
                const float* src = ss ? (xk + ci*Ln + gl) : xk;
                unsigned daddr = (unsigned)__cvta_generic_to_shared(
                                     tile + (s << 13) + (ci << 7) + jc);
                asm volatile("cp.async.ca.shared.global [%0], [%1], 16, %2;"
                             :: "r"(daddr), "l"(src), "r"(ss) : "memory");
            }
            asm volatile("cp.async.commit_group;" ::: "memory");
            asm volatile("cp.async.wait_group 0;" ::: "memory");
        } else {
#pragma unroll 4
            for (int i = tid; i < 3*Cn*TL; i += LTHREADS){
                int s  = i >> 13;
                int r  = i & 8191;
                int ci = r >> 7; int j = r & 127;
                int gl = l0 + j + (s - 1) * dil;
                float val = 0.f;
                if ((unsigned)gl < (unsigned)Ln) val = xk[ci*Ln + gl];
                tile[i] = val;
            }
        }
    }
    __syncthreads();   // S1 (t=0)

    for (int t = 0; t < Tn; t++){
        const float* xk_next = x_in + ((size_t)((t+1)*Bn + b)) * Cn * Ln;

        // ---- conv: 16 couts x 4 l, this timestep ----
        unsigned long long acc[4][4];   // [m-pair p][l]
        {
            const ulonglong2* fb = (const ulonglong2*)(cb + (jg << 3));
            ulonglong2 fbA = fb[0], fbB = fb[1];
#pragma unroll
            for (int l = 0; l < 4; l++){
                acc[0][l] = fbA.x; acc[1][l] = fbA.y;
                acc[2][l] = fbB.x; acc[3][l] = fbB.y;
            }
        }
#pragma unroll 2
        for (int ci = 0; ci < Cn; ci++){
            const float* trow = tile + (ci << 7);
            ulonglong2 xa = *(const ulonglong2*)(trow + jA);
            ulonglong2 xz = *(const ulonglong2*)(trow + 8192 + jA);
            ulonglong2 xp = *(const ulonglong2*)(trow + 16384 + jA);
            const float* wrow = wc8 + (ci*16 + jg)*24;
#pragma unroll
            for (int tap = 0; tap < 3; tap++){
                ulonglong2 wA = *(const ulonglong2*)(wrow + tap*8);
                ulonglong2 wB = *(const ulonglong2*)(wrow + tap*8 + 4);
                ulonglong2 xs_ = (tap == 0) ? xa : (tap == 1) ? xz : xp;
                unsigned long long xd0 = pk2(lo32(xs_.x));
                unsigned long long xd1 = pk2(hi32(xs_.x));
                unsigned long long xd2 = pk2(lo32(xs_.y));
                unsigned long long xd3 = pk2(hi32(xs_.y));
                f2fma(acc[0][0], wA.x, xd0); f2fma(acc[0][1], wA.x, xd1);
                f2fma(acc[0][2], wA.x, xd2); f2fma(acc[0][3], wA.x, xd3);
                f2fma(acc[1][0], wA.y, xd0); f2fma(acc[1][1], wA.y, xd1);
                f2fma(acc[1][2], wA.y, xd2); f2fma(acc[1][3], wA.y, xd3);
                f2fma(acc[2][0], wB.x, xd0); f2fma(acc[2][1], wB.x, xd1);
                f2fma(acc[2][2], wB.x, xd2); f2fma(acc[2][3], wB.x, xd3);
                f2fma(acc[3][0], wB.y, xd0); f2fma(acc[3][1], wB.y, xd1);
                f2fma(acc[3][2], wB.y, xd2); f2fma(acc[3][3], wB.y, xd3);
            }
        }

        // ---- LIF + gating (ALL threads, own accs) ----
        float glo[2][4], ghi[2][4];
#pragma unroll
        for (int p = 0; p < 2; p++){
#pragma unroll
            for (int l = 0; l < 4; l++){
                float ag_lo = lo32(acc[p][l]),   ag_hi = hi32(acc[p][l]);
                float af_lo = lo32(acc[p+2][l]), af_hi = hi32(acc[p+2][l]);

                if (edge){
                    int gl = l0 + jA + l;
                    float f0 = (gl < dil) ? 1.f : 0.f;
                    float f2 = (gl >= Ln - dil) ? 1.f : 0.f;
                    int clo = jg + 32*p;
                    ag_lo -= f0*ck[clo]      + f2*ck[256+clo];
                    ag_hi -= f0*ck[clo+16]   + f2*ck[256+clo+16];
                    af_lo -= f0*ck[clo+64]   + f2*ck[256+clo+64];
                    af_hi -= f0*ck[clo+80]   + f2*ck[256+clo+80];
                }

                int idx = p*4 + l;
                float sg, sf;
                lif_step(vG0[idx], ag_lo, sg); lif_step(vF0[idx], af_lo, sf);
                glo[p][l] = ((sg > 0.f) ? SG1 : 0.5f) * ((sf > 0.f) ? TH1 : 0.f);
                lif_step(vG1[idx], ag_hi, sg); lif_step(vF1[idx], af_hi, sf);
                ghi[p][l] = ((sg > 0.f) ? SG1 : 0.5f) * ((sf > 0.f) ? TH1 : 0.f);
            }
        }
        __syncthreads();   // S2: conv tile reads done -> s0 overlay safe, s2 dead

#pragma unroll
        for (int p = 0; p < 2; p++){
            int chlo = jg + 32*p;
            int chhi = chlo + 16;
            *(float4*)(tile + (chlo << 7) + jA) = make_float4(glo[p][0], glo[p][1], glo[p][2], glo[p][3]);
            *(float4*)(tile + (chhi << 7) + jA) = make_float4(ghi[p][0], ghi[p][1], ghi[p][2], ghi[p][3]);
        }
        __syncthreads();   // S3: gated overlay visible

        // ---- EARLY staging: next pass's s2 region, overlapped with 1x1 ----
        if (t < Tn-1 && async_path){
#pragma unroll
            for (int w = 0; w < 4; w++){
                int q  = tid + w*LTHREADS;
                int ci = q >> 5;
                int jc = (q & 31) << 2;
                int gl = l0 + dil + jc;
                unsigned ss = ((unsigned)gl <= 4092u) ? 16u : 0u;
                const float* src = ss ? (xk_next + ci*Ln + gl) : xk_next;
                unsigned daddr = (unsigned)__cvta_generic_to_shared(
                                     tile + (2 << 13) + (ci << 7) + jc);
                asm volatile("cp.async.ca.shared.global [%0], [%1], 16, %2;"
                             :: "r"(daddr), "l"(src), "r"(ss) : "memory");
            }
            asm volatile("cp.async.commit_group;" ::: "memory");
        }

        // ---- skip / res 1x1: 4 couts (jg+16m1) x 4 l ----
        unsigned long long sk[2][4], rs[2][4];
#pragma unroll
        for (int p = 0; p < 2; p++)
#pragma unroll
        for (int l = 0; l < 4; l++){ sk[p][l] = 0ull; rs[p][l] = 0ull; }

#pragma unroll 4
        for (int ci = 0; ci < Cn; ci++){
            ulonglong2 g = *(const ulonglong2*)(tile + (ci << 7) + jA);
            unsigned long long gd0 = pk2(lo32(g.x));
            unsigned long long gd1 = pk2(hi32(g.x));
            unsigned long long gd2 = pk2(lo32(g.y));
            unsigned long long gd3 = pk2(hi32(g.y));
            const float* wb = wskr + (ci*16 + jg)*8;
            ulonglong2 wsv = *(const ulonglong2*)(wb);
            ulonglong2 wrv = *(const ulonglong2*)(wb + 4);
            f2fma(sk[0][0], wsv.x, gd0); f2fma(sk[0][1], wsv.x, gd1);
            f2fma(sk[0][2], wsv.x, gd2); f2fma(sk[0][3], wsv.x, gd3);
            f2fma(sk[1][0], wsv.y, gd0); f2fma(sk[1][1], wsv.y, gd1);
            f2fma(sk[1][2], wsv.y, gd2); f2fma(sk[1][3], wsv.y, gd3);
            f2fma(rs[0][0], wrv.x, gd0); f2fma(rs[0][1], wrv.x, gd1);
            f2fma(rs[0][2], wrv.x, gd2); f2fma(rs[0][3], wrv.x, gd3);
            f2fma(rs[1][0], wrv.y, gd0); f2fma(rs[1][1], wrv.y, gd1);
            f2fma(rs[1][2], wrv.y, gd2); f2fma(rs[1][3], wrv.y, gd3);
        }

        // ---- global update: 4 ch x 4 l ----
        {
#pragma unroll
            for (int m = 0; m < 4; m++){
                int ch = jg + 16*m;
                int p = m >> 1;
                bool hi = (m & 1);
                float s0 = hi ? hi32(sk[p][0]) : lo32(sk[p][0]);
                float s1 = hi ? hi32(sk[p][1]) : lo32(sk[p][1]);
                float s2 = hi ? hi32(sk[p][2]) : lo32(sk[p][2]);
                float s3 = hi ? hi32(sk[p][3]) : lo32(sk[p][3]);
                float r0 = hi ? hi32(rs[p][0]) : lo32(rs[p][0]);
                float r1 = hi ? hi32(rs[p][1]) : lo32(rs[p][1]);
                float r2 = hi ? hi32(rs[p][2]) : lo32(rs[p][2]);
                float r3 = hi ? hi32(rs[p][3]) : lo32(rs[p][3]);
                float sbp = sbv[ch], rbp = rbv[ch];
                size_t gbase = ((size_t)(t*Bn + b)*Cn + ch)*Ln + l0 + jA;

                float4 sv = make_float4(s0+sbp, s1+sbp, s2+sbp, s3+sbp);
                float4* skA = (float4*)(g_skip + gbase);
                if (layer != 0){
                    float4 o0 = *skA;
                    sv.x += o0.x; sv.y += o0.y; sv.z += o0.z; sv.w += o0.w;
                }
                *skA = sv;

                if (layer != NLAYERS-1){
                    float4 a0 = *(const float4*)(tile + 8192 + (ch << 7) + jA);
                    a0.x += r0+rbp; a0.y += r1+rbp; a0.z += r2+rbp; a0.w += r3+rbp;
                    *(float4*)(x_out + gbase) = a0;
                }
            }
        }
        __syncthreads();   // S4: all tile reads done -> s0/s1 staging safe

        // ---- LATE staging: next pass's s0 + s1 regions ----
        if (t < Tn-1){
            if (async_path){
#pragma unroll
                for (int w = 0; w < 8; w++){
                    int q  = tid + w*LTHREADS;
                    int s  = q >> 11;            // 0 or 1
                    int r  = q & 2047;
                    int ci = r >> 5;
                    int jc = (r & 31) << 2;
                    int gl = l0 + (s - 1)*dil + jc;
                    unsigned ss = ((unsigned)gl <= 4092u) ? 16u : 0u;
                    const float* src = ss ? (xk_next + ci*Ln + gl) : xk_next;
                    unsigned daddr = (unsigned)__cvta_generic_to_shared(
                                         tile + (s << 13) + (ci << 7) + jc);
                    asm volatile("cp.async.ca.shared.global [%0], [%1], 16, %2;"
                                 :: "r"(daddr), "l"(src), "r"(ss) : "memory");
                }
                asm volatile("cp.async.commit_group;" ::: "memory");
                asm volatile("cp.async.wait_group 0;" ::: "memory");
            } else {
#pragma unroll 4
                for (int i = tid; i < 3*Cn*TL; i += LTHREADS){
                    int s  = i >> 13;
                    int r  = i & 8191;
                    int ci = r >> 7; int j = r & 127;
                    int gl = l0 + j + (s - 1) * dil;
                    float val = 0.f;
                    if ((unsigned)gl < (unsigned)Ln) val = xk_next[ci*Ln + gl];
                    tile[i] = val;
                }
            }
            __syncthreads();   // S1 of next pass
        }
    }
}

// ---------------- out stage 1: relu(skip) -> 1x1 conv, fully parallel over (t,b,l) ----
__global__ void __launch_bounds__(256) out_stage1(const float* __restrict__ wout,
                                                  const float* __restrict__ bout){
    int g = blockIdx.x * 256 + threadIdx.x;       // 0..65535 = (t,b,l)
    int tb = g >> 12;                              // t*Bn + b
    int l  = g & (Ln - 1);
    float acc = bout[0];
    const float* sk = g_skip + ((size_t)tb)*Cn*Ln + l;
    for (int c = 0; c < Cn; c++){
        float s = sk[(size_t)c*Ln];
        s = (s > 0.f) ? s : 0.f;
        acc += wout[c] * s;
    }
    g_xA[g] = acc;   // scratch layout [t][b][l]
}

// ---------------- out stage 2: LIF over t + sum ----------------
__global__ void __launch_bounds__(256) out_stage2(float* __restrict__ out){
    int g = blockIdx.x * 256 + threadIdx.x;       // 0..16383 = (b,l)
    float v = 0.f, ssum = 0.f;
#pragma unroll
    for (int t = 0; t < Tn; t++){
        float acc = g_xA[t*(Bn*Ln) + g];
        float sp; lif_step(v, acc, sp);
        ssum += sp;
    }
    out[g] = ssum;
}

// ---------------- launch ----------------
extern "C" void kernel_launch(void* const* d_in, const int* in_sizes, int n_in,
                              void* d_out, int out_size){
    const float* audio   = (const float*)d_in[0];
    const int*   dstep   = (const int*)  d_in[1];
    const float* W_in    = (const float*)d_in[2];
    const float* b_in    = (const float*)d_in[3];
    const float* demb_w1 = (const float*)d_in[4];
    const float* demb_b1 = (const float*)d_in[5];
    const float* demb_w2 = (const float*)d_in[6];
    const float* demb_b2 = (const float*)d_in[7];
    const float* dproj_w = (const float*)d_in[8];
    const float* dproj_b = (const float*)d_in[9];
    const float* conv_w  = (const float*)d_in[10];
    const float* conv_b  = (const float*)d_in[11];
    const float* skip_w  = (const float*)d_in[12];
    const float* skip_b  = (const float*)d_in[13];
    const float* res_w   = (const float*)d_in[14];
    const float* res_b   = (const float*)d_in[15];
    const float* W_out   = (const float*)d_in[16];
    const float* b_out   = (const float*)d_in[17];

    const int SMEM_BYTES = 58048 * 4;   // 232192  (audited: 58048 floats)
    cudaFuncSetAttribute((const void*)layer_kernel,
                         cudaFuncAttributeMaxDynamicSharedMemorySize, SMEM_BYTES);

    enc_kernel<<<(Bn*Ln)/256, 256>>>(audio, W_in, b_in);

    proj_all_kernel<<<NLAYERS, 256>>>(dstep, demb_w1, demb_b1, demb_w2, demb_b2,
                                      dproj_w, dproj_b);

    int flip = 0;
    for (int i = 0; i < NLAYERS; i++){
        layer_kernel<<<dim3(Ln/TL, Bn), LTHREADS, SMEM_BYTES>>>(flip, i,
                                conv_w + i*2*Cn*Cn*3, conv_b + i*2*Cn,
                                skip_w + i*Cn*Cn,     skip_b + i*Cn,
                                res_w  + i*Cn*Cn,     res_b  + i*Cn,
                                1 << i);
        flip ^= 1;
    }

    out_stage1<<<(Tn*Bn*Ln)/256, 256>>>(W_out, b_out);
    out_stage2<<<(Bn*Ln)/256, 256>>>((float*)d_out);
}